// round 8
// baseline (speedup 1.0000x reference)
#include <cuda_runtime.h>
#include <cuda_bf16.h>
#include <math.h>
#include <cstdint>

#define SEQ 2048
#define DM  2048
#define NH  16
#define DQK 128
#define DV  128
#define NCAT 6144   // q|k|v concatenated head-columns

// ---------------- helpers ----------------------------------------------------
__device__ __forceinline__ uint32_t smem_u32(const void* p) {
    uint32_t a;
    asm("{ .reg .u64 t; cvta.to.shared.u64 t, %1; cvt.u32.u64 %0, t; }"
        : "=r"(a) : "l"(p));
    return a;
}

#define CP_ASYNC16(dst, src) \
    asm volatile("cp.async.cg.shared.global [%0], [%1], 16;" :: "r"(dst), "l"(src))
#define CP_COMMIT() asm volatile("cp.async.commit_group;" ::: "memory")
#define CP_WAIT(n)  asm volatile("cp.async.wait_group %0;" :: "n"(n) : "memory")

__device__ __forceinline__ void ldsm4(uint32_t* r, uint32_t addr) {
    asm volatile("ldmatrix.sync.aligned.m8n8.x4.shared.b16 {%0,%1,%2,%3}, [%4];"
                 : "=r"(r[0]), "=r"(r[1]), "=r"(r[2]), "=r"(r[3]) : "r"(addr));
}

__device__ __forceinline__ void mma_bf16(float* d, const uint32_t* a,
                                         uint32_t b0, uint32_t b1) {
    asm volatile(
        "mma.sync.aligned.m16n8k16.row.col.f32.bf16.bf16.f32 "
        "{%0,%1,%2,%3}, {%4,%5,%6,%7}, {%8,%9}, {%0,%1,%2,%3};"
        : "+f"(d[0]), "+f"(d[1]), "+f"(d[2]), "+f"(d[3])
        : "r"(a[0]), "r"(a[1]), "r"(a[2]), "r"(a[3]), "r"(b0), "r"(b1));
}

// ---------------- scratch (device globals) ----------------------------------
__device__ __align__(256) __nv_bfloat16 g_xs[2ull * SEQ * DM];    // 16 MB (2 planes)
__device__ __align__(256) __nv_bfloat16 g_wt[2ull * NCAT * DM];   // 50 MB
__device__ __align__(256) __nv_bfloat16 g_ot[2ull * DM * DM];     // 16 MB
__device__ __align__(256) __nv_bfloat16 g_ys[2ull * SEQ * DM];    // 16 MB
__device__ __align__(256) float g_pqkv[(size_t)SEQ * NCAT];       // 50 MB
__device__ __align__(256) float g_ycat[(size_t)SEQ * NH * DV];    // 16 MB
__device__ float g_sin[SEQ * 64];
__device__ float g_cos[SEQ * 64];

// ---------------- bf16x2 split ----------------------------------------------
__device__ __forceinline__ void split2(float x, __nv_bfloat16& b0, __nv_bfloat16& b1) {
    b0 = __float2bfloat16(x);
    float r = x - __bfloat162float(b0);
    b1 = __float2bfloat16(r);
}

// ---------------- RoPE sin/cos table ----------------------------------------
__global__ void rope_table_kernel(const float* __restrict__ theta_p) {
    int idx = blockIdx.x * blockDim.x + threadIdx.x;
    if (idx >= SEQ * 64) return;
    int j = idx & 63;
    int s = idx >> 6;
    float theta = *theta_p;
    float rate = theta * (-(float)j / 64.0f);
    float rot  = (float)s * rate;
    double rd = (double)rot;
    g_sin[idx] = (float)sin(rd);
    g_cos[idx] = (float)cos(rd);
}

// ---------------- split kernels ---------------------------------------------
__global__ void split_x_kernel(const float* __restrict__ x) {
    int i = blockIdx.x * blockDim.x + threadIdx.x;
    const size_t N = (size_t)SEQ * DM;
    __nv_bfloat16 b0, b1;
    split2(x[i], b0, b1);
    g_xs[i] = b0; g_xs[N + i] = b1;
}
__global__ void split_y_kernel() {
    int i = blockIdx.x * blockDim.x + threadIdx.x;
    const size_t N = (size_t)SEQ * DM;
    __nv_bfloat16 b0, b1;
    split2(g_ycat[i], b0, b1);
    g_ys[i] = b0; g_ys[N + i] = b1;
}

// ---------------- weight transpose + split ----------------------------------
// q/k/v[h][dm][e] -> g_wt[p][n = which*2048 + h*128 + e][dm]
__global__ void trans_w_kernel(const float* __restrict__ q,
                               const float* __restrict__ k,
                               const float* __restrict__ v) {
    __shared__ float t[32][33];
    int bz = blockIdx.z;
    int which = bz >> 4, h = bz & 15;
    const float* W = (which == 0 ? q : which == 1 ? k : v) + (size_t)h * DM * DQK;
    int kk0 = blockIdx.x * 32, e0 = blockIdx.y * 32;
    int tx = threadIdx.x, ty = threadIdx.y;
    const size_t WS = (size_t)NCAT * DM;
#pragma unroll
    for (int r = 0; r < 4; r++)
        t[ty + 8 * r][tx] = W[(size_t)(kk0 + ty + 8 * r) * DQK + e0 + tx];
    __syncthreads();
    size_t nbase = (size_t)which * 2048 + h * 128 + e0;
#pragma unroll
    for (int r = 0; r < 4; r++) {
        float xv = t[tx][ty + 8 * r];
        __nv_bfloat16 b0, b1;
        split2(xv, b0, b1);
        size_t o = (nbase + ty + 8 * r) * DM + kk0 + tx;
        g_wt[o] = b0; g_wt[WS + o] = b1;
    }
}
// o[h][v][dm] -> g_ot[p][n = dm][k = h*128 + v]
__global__ void trans_o_kernel(const float* __restrict__ o) {
    __shared__ float t[32][33];
    int h = blockIdx.z;
    const float* O = o + (size_t)h * DV * DM;
    int dm0 = blockIdx.x * 32, v0 = blockIdx.y * 32;
    int tx = threadIdx.x, ty = threadIdx.y;
    const size_t OS = (size_t)DM * DM;
#pragma unroll
    for (int r = 0; r < 4; r++)
        t[ty + 8 * r][tx] = O[(size_t)(v0 + ty + 8 * r) * DM + dm0 + tx];
    __syncthreads();
#pragma unroll
    for (int r = 0; r < 4; r++) {
        float xv = t[tx][ty + 8 * r];
        __nv_bfloat16 b0, b1;
        split2(xv, b0, b1);
        size_t oo = (size_t)(dm0 + ty + 8 * r) * DM + h * 128 + v0 + tx;
        g_ot[oo] = b0; g_ot[OS + oo] = b1;
    }
}

// ---------------- bf16x2 mma.sync GEMM ---------------------------------------
// C[m0:+256, n0:+128] = alpha * sum_k A[m][k]*B[n][k],  K=2048
// A,B each 2 bf16 planes, k-contiguous rows.
// CTA: 256 threads = 8 warps (wm 0..3 x wn 0..1), warp tile 64x64.
// smem per stage: A 2x32KB + B 2x16KB = 96KB; double buffered = 192KB.
#define GSM_BYTES (2 * 98304)

__global__ void __launch_bounds__(256, 1) gemm2_kernel(float* Cout, int mode) {
    extern __shared__ char gsm[];
    const __nv_bfloat16 *A3, *B3;
    size_t As, Bs;
    float* C; int ldc; float alpha;
    if (mode == 0) {
        A3 = g_xs; As = (size_t)SEQ * DM;
        B3 = g_wt; Bs = (size_t)NCAT * DM;
        C = g_pqkv; ldc = NCAT; alpha = 1.0f;
    } else {
        A3 = g_ys; As = (size_t)SEQ * DM;
        B3 = g_ot; Bs = (size_t)DM * DM;
        C = Cout; ldc = DM; alpha = 1.0f / 2048.0f;
    }

    uint32_t sb = smem_u32(gsm);
    int tid = threadIdx.x;
    int lane = tid & 31, wid = tid >> 5;
    int wm = wid >> 1, wn = wid & 1;
    int m0 = blockIdx.x * 256, n0 = blockIdx.y * 128;

    float acc[4][8][4];
#pragma unroll
    for (int i = 0; i < 4; i++)
#pragma unroll
        for (int j = 0; j < 8; j++)
#pragma unroll
            for (int r = 0; r < 4; r++) acc[i][j][r] = 0.0f;

    // ---- loader lambda (cp.async, swizzled stores) ----
    auto load_stage = [&](int s, int kc) {
        int k0 = kc * 64;
#pragma unroll
        for (int p = 0; p < 2; p++) {
            const __nv_bfloat16* gp = A3 + p * As + (size_t)m0 * DM + k0;
            uint32_t base = sb + s * 98304 + p * 32768;
#pragma unroll
            for (int i = 0; i < 8; i++) {
                int idx = i * 256 + tid;          // 0..2047
                int row = idx >> 3, c = idx & 7;
                uint32_t dst = base + row * 128 + ((c ^ (row & 7)) << 4);
                CP_ASYNC16(dst, gp + (size_t)row * DM + c * 8);
            }
        }
#pragma unroll
        for (int p = 0; p < 2; p++) {
            const __nv_bfloat16* gp = B3 + p * Bs + (size_t)n0 * DM + k0;
            uint32_t base = sb + s * 98304 + 65536 + p * 16384;
#pragma unroll
            for (int i = 0; i < 4; i++) {
                int idx = i * 256 + tid;          // 0..1023
                int row = idx >> 3, c = idx & 7;
                uint32_t dst = base + row * 128 + ((c ^ (row & 7)) << 4);
                CP_ASYNC16(dst, gp + (size_t)row * DM + c * 8);
            }
        }
    };

    load_stage(0, 0); CP_COMMIT();

    for (int kc = 0; kc < 32; kc++) {
        int s = kc & 1;
        if (kc + 1 < 32) { load_stage(s ^ 1, kc + 1); CP_COMMIT(); CP_WAIT(1); }
        else            { CP_WAIT(0); }
        __syncthreads();

        uint32_t stage = sb + s * 98304;
#pragma unroll
        for (int ks = 0; ks < 4; ks++) {
            uint32_t a[2][4][4];
#pragma unroll
            for (int p = 0; p < 2; p++)
#pragma unroll
                for (int mf = 0; mf < 4; mf++) {
                    int row = wm * 64 + mf * 16 + (lane & 15);
                    int c = ks * 2 + ((lane >> 4) & 1);
                    uint32_t addr = stage + p * 32768 + row * 128 +
                                    ((c ^ (row & 7)) << 4);
                    ldsm4(a[p][mf], addr);
                }
            uint32_t b[2][4][4];
#pragma unroll
            for (int p = 0; p < 2; p++)
#pragma unroll
                for (int nf2 = 0; nf2 < 4; nf2++) {
                    int row = wn * 64 + nf2 * 16 + (lane & 7) + ((lane >> 4) & 1) * 8;
                    int c = ks * 2 + ((lane >> 3) & 1);
                    uint32_t addr = stage + 65536 + p * 16384 + row * 128 +
                                    ((c ^ (row & 7)) << 4);
                    ldsm4(b[p][nf2], addr);
                }
            // products: (A0,B0), (A0,B1), (A1,B0)
#pragma unroll
            for (int mf = 0; mf < 4; mf++)
#pragma unroll
                for (int nf2 = 0; nf2 < 4; nf2++) {
                    mma_bf16(acc[mf][2 * nf2 + 0], a[0][mf], b[0][nf2][0], b[0][nf2][1]);
                    mma_bf16(acc[mf][2 * nf2 + 1], a[0][mf], b[0][nf2][2], b[0][nf2][3]);
                    mma_bf16(acc[mf][2 * nf2 + 0], a[0][mf], b[1][nf2][0], b[1][nf2][1]);
                    mma_bf16(acc[mf][2 * nf2 + 1], a[0][mf], b[1][nf2][2], b[1][nf2][3]);
                    mma_bf16(acc[mf][2 * nf2 + 0], a[1][mf], b[0][nf2][0], b[0][nf2][1]);
                    mma_bf16(acc[mf][2 * nf2 + 1], a[1][mf], b[0][nf2][2], b[0][nf2][3]);
                }
        }
        __syncthreads();
    }

    // epilogue
#pragma unroll
    for (int mf = 0; mf < 4; mf++) {
        int r0 = m0 + wm * 64 + mf * 16 + (lane >> 2);
#pragma unroll
        for (int nf = 0; nf < 8; nf++) {
            int cb = n0 + wn * 64 + nf * 8 + (lane & 3) * 2;
            float2 v01 = make_float2(acc[mf][nf][0] * alpha, acc[mf][nf][1] * alpha);
            float2 v23 = make_float2(acc[mf][nf][2] * alpha, acc[mf][nf][3] * alpha);
            *(float2*)&C[(size_t)r0 * ldc + cb] = v01;
            *(float2*)&C[(size_t)(r0 + 8) * ldc + cb] = v23;
        }
    }
}

// ---------------- RoPE apply (in place on q,k cols of g_pqkv) ----------------
__global__ void rope_apply_kernel() {
    int g = blockIdx.x * blockDim.x + threadIdx.x;   // 2^22 threads
    int j = g & 63;
    int s = (g >> 6) & (SEQ - 1);
    int h = (g >> 17) & (NH - 1);
    int t = g >> 21;                                  // 0=q, 1=k
    float* row = g_pqkv + (size_t)s * NCAT + t * 2048 + h * 128;
    float x1 = row[j];
    float x2 = row[j + 64];
    float sn = g_sin[s * 64 + j];
    float cs = g_cos[s * 64 + j];
    const float dq4 = 3.3635856610148585f;  // 128^0.25
    row[j]      = (cs * x1 - sn * x2) / dq4;
    row[j + 64] = (sn * x1 + cs * x2) / dq4;
}

// ---------------- flash attention (fp32 SIMT, LPT order) ---------------------
#define LQ 132
#define LK 68
#define LV 132
#define LP 132
#define ATTN_SMEM ((128 * LQ + 128 * LK + 64 * LV + 64 * LP) * 4)

__global__ void attn_kernel() {
    extern __shared__ float attn_smem[];
    float* sQt = attn_smem;
    float* sKt = sQt + 128 * LQ;
    float* sV  = sKt + 128 * LK;
    float* sPt = sV + 64 * LV;

    int h  = blockIdx.x;
    int qt = 15 - blockIdx.y;        // heavy q-tiles scheduled first (LPT)
    int tid = threadIdx.x;
    int kx = tid & 15;
    int qy = tid >> 4;
    int q0 = qt * 128;

    const float* Q  = g_pqkv + (size_t)q0 * NCAT + h * 128;
    const float* Kb = g_pqkv + 2048 + h * 128;
    const float* Vb = g_pqkv + 4096 + h * 128;

#pragma unroll
    for (int it = 0; it < 16; it++) {
        int idx = it * 256 + tid;
        int qr = idx >> 5;
        int d0 = (idx & 31) * 4;
        float4 a = *(const float4*)&Q[(size_t)qr * NCAT + d0];
        sQt[(d0 + 0) * LQ + qr] = a.x;
        sQt[(d0 + 1) * LQ + qr] = a.y;
        sQt[(d0 + 2) * LQ + qr] = a.z;
        sQt[(d0 + 3) * LQ + qr] = a.w;
    }

    int rows[8];
#pragma unroll
    for (int i = 0; i < 8; i++)
        rows[i] = (i < 4 ? qy * 4 + i : 64 + qy * 4 + (i - 4));

    float m_run[8], l_run[8], y[8][8];
#pragma unroll
    for (int i = 0; i < 8; i++) {
        m_run[i] = -INFINITY;
        l_run[i] = 0.0f;
#pragma unroll
        for (int j = 0; j < 8; j++) y[i][j] = 0.0f;
    }

    int nkt = 2 * qt + 2;
    for (int kt = 0; kt < nkt; kt++) {
        int kbase = kt * 64;
        __syncthreads();
#pragma unroll
        for (int it = 0; it < 8; it++) {
            int idx = it * 256 + tid;
            int kr = idx >> 5;
            int d0 = (idx & 31) * 4;
            float4 a = *(const float4*)&Kb[(size_t)(kbase + kr) * NCAT + d0];
            sKt[(d0 + 0) * LK + kr] = a.x;
            sKt[(d0 + 1) * LK + kr] = a.y;
            sKt[(d0 + 2) * LK + kr] = a.z;
            sKt[(d0 + 3) * LK + kr] = a.w;
            *(float4*)&sV[kr * LV + d0] =
                *(const float4*)&Vb[(size_t)(kbase + kr) * NCAT + d0];
        }
        __syncthreads();

        float acc[8][4];
#pragma unroll
        for (int i = 0; i < 8; i++)
#pragma unroll
            for (int j = 0; j < 4; j++) acc[i][j] = 0.0f;

#pragma unroll 8
        for (int d = 0; d < 128; d++) {
            float4 a0 = *(float4*)&sQt[d * LQ + qy * 4];
            float4 a1 = *(float4*)&sQt[d * LQ + 64 + qy * 4];
            float4 b  = *(float4*)&sKt[d * LK + kx * 4];
            float a[8] = {a0.x, a0.y, a0.z, a0.w, a1.x, a1.y, a1.z, a1.w};
            float bb[4] = {b.x, b.y, b.z, b.w};
#pragma unroll
            for (int i = 0; i < 8; i++)
#pragma unroll
                for (int j = 0; j < 4; j++)
                    acc[i][j] = fmaf(a[i], bb[j], acc[i][j]);
        }

        float corr[8];
#pragma unroll
        for (int i = 0; i < 8; i++) {
            int qg = q0 + rows[i];
#pragma unroll
            for (int j = 0; j < 4; j++) {
                int kg = kbase + kx * 4 + j;
                if (kg > qg) acc[i][j] -= 1.0e9f;
            }
            float mx = fmaxf(fmaxf(acc[i][0], acc[i][1]),
                             fmaxf(acc[i][2], acc[i][3]));
#pragma unroll
            for (int off = 8; off > 0; off >>= 1)
                mx = fmaxf(mx, __shfl_xor_sync(0xffffffffu, mx, off));
            float mnew = fmaxf(m_run[i], mx);
            float c = expf(m_run[i] - mnew);
            float ls = 0.0f;
#pragma unroll
            for (int j = 0; j < 4; j++) {
                float p = expf(acc[i][j] - mnew);
                ls += p;
                sPt[(kx * 4 + j) * LP + rows[i]] = p;
            }
#pragma unroll
            for (int off = 8; off > 0; off >>= 1)
                ls += __shfl_xor_sync(0xffffffffu, ls, off);
            l_run[i] = l_run[i] * c + ls;
            m_run[i] = mnew;
            corr[i] = c;
        }
#pragma unroll
        for (int i = 0; i < 8; i++)
#pragma unroll
            for (int j = 0; j < 8; j++) y[i][j] *= corr[i];

        __syncthreads();

#pragma unroll 4
        for (int k = 0; k < 64; k++) {
            float4 p0 = *(float4*)&sPt[k * LP + qy * 4];
            float4 p1 = *(float4*)&sPt[k * LP + 64 + qy * 4];
            float4 v0 = *(float4*)&sV[k * LV + kx * 4];
            float4 v1 = *(float4*)&sV[k * LV + 64 + kx * 4];
            float p[8]  = {p0.x, p0.y, p0.z, p0.w, p1.x, p1.y, p1.z, p1.w};
            float vv[8] = {v0.x, v0.y, v0.z, v0.w, v1.x, v1.y, v1.z, v1.w};
#pragma unroll
            for (int i = 0; i < 8; i++)
#pragma unroll
                for (int j = 0; j < 8; j++)
                    y[i][j] = fmaf(p[i], vv[j], y[i][j]);
        }
    }

#pragma unroll
    for (int i = 0; i < 8; i++) {
        float inv = 1.0f / l_run[i];
        int r = q0 + rows[i];
        float4 o0 = make_float4(y[i][0] * inv, y[i][1] * inv,
                                y[i][2] * inv, y[i][3] * inv);
        float4 o1 = make_float4(y[i][4] * inv, y[i][5] * inv,
                                y[i][6] * inv, y[i][7] * inv);
        size_t basep = (size_t)r * (NH * DV) + h * DV;
        *(float4*)&g_ycat[basep + kx * 4] = o0;
        *(float4*)&g_ycat[basep + 64 + kx * 4] = o1;
    }
}

// ---------------- launch ----------------------------------------------------
extern "C" void kernel_launch(void* const* d_in, const int* in_sizes, int n_in,
                              void* d_out, int out_size) {
    const float* x     = (const float*)d_in[0];
    const float* q     = (const float*)d_in[1];
    const float* k     = (const float*)d_in[2];
    const float* v     = (const float*)d_in[3];
    const float* o     = (const float*)d_in[4];
    const float* theta = (const float*)d_in[5];
    float* z = (float*)d_out;

    cudaFuncSetAttribute(attn_kernel,
                         cudaFuncAttributeMaxDynamicSharedMemorySize, ATTN_SMEM);
    cudaFuncSetAttribute(gemm2_kernel,
                         cudaFuncAttributeMaxDynamicSharedMemorySize, GSM_BYTES);

    rope_table_kernel<<<(SEQ * 64 + 255) / 256, 256>>>(theta);
    split_x_kernel<<<(SEQ * DM) / 256, 256>>>(x);
    trans_w_kernel<<<dim3(64, 4, 48), dim3(32, 8)>>>(q, k, v);
    trans_o_kernel<<<dim3(64, 4, 16), dim3(32, 8)>>>(o);
    gemm2_kernel<<<dim3(8, 48), 256, GSM_BYTES>>>(nullptr, 0);
    rope_apply_kernel<<<(2 * NH * SEQ * 64) / 256, 256>>>();
    attn_kernel<<<dim3(NH, 16), 256, ATTN_SMEM>>>();
    split_y_kernel<<<(SEQ * DM) / 256, 256>>>();
    gemm2_kernel<<<dim3(8, 16), 256, GSM_BYTES>>>(z, 1);
}

// round 9
// speedup vs baseline: 1.4376x; 1.4376x over previous
#include <cuda_runtime.h>
#include <cuda_bf16.h>
#include <math.h>
#include <cstdint>

#define SEQ 2048
#define DM  2048
#define NH  16
#define DQK 128
#define DV  128
#define NCAT 6144   // q|k|v concatenated head-columns

// ---------------- helpers ----------------------------------------------------
__device__ __forceinline__ uint32_t smem_u32(const void* p) {
    uint32_t a;
    asm("{ .reg .u64 t; cvta.to.shared.u64 t, %1; cvt.u32.u64 %0, t; }"
        : "=r"(a) : "l"(p));
    return a;
}

#define CP_ASYNC16(dst, src) \
    asm volatile("cp.async.cg.shared.global [%0], [%1], 16;" :: "r"(dst), "l"(src))
#define CP_COMMIT() asm volatile("cp.async.commit_group;" ::: "memory")
#define CP_WAIT(n)  asm volatile("cp.async.wait_group %0;" :: "n"(n) : "memory")

__device__ __forceinline__ void ldsm4(uint32_t* r, uint32_t addr) {
    asm volatile("ldmatrix.sync.aligned.m8n8.x4.shared.b16 {%0,%1,%2,%3}, [%4];"
                 : "=r"(r[0]), "=r"(r[1]), "=r"(r[2]), "=r"(r[3]) : "r"(addr));
}
__device__ __forceinline__ void ldsm4t(uint32_t* r, uint32_t addr) {
    asm volatile("ldmatrix.sync.aligned.m8n8.x4.trans.shared.b16 {%0,%1,%2,%3}, [%4];"
                 : "=r"(r[0]), "=r"(r[1]), "=r"(r[2]), "=r"(r[3]) : "r"(addr));
}

__device__ __forceinline__ void mma_bf16(float* d, const uint32_t* a,
                                         uint32_t b0, uint32_t b1) {
    asm volatile(
        "mma.sync.aligned.m16n8k16.row.col.f32.bf16.bf16.f32 "
        "{%0,%1,%2,%3}, {%4,%5,%6,%7}, {%8,%9}, {%0,%1,%2,%3};"
        : "+f"(d[0]), "+f"(d[1]), "+f"(d[2]), "+f"(d[3])
        : "r"(a[0]), "r"(a[1]), "r"(a[2]), "r"(a[3]), "r"(b0), "r"(b1));
}

__device__ __forceinline__ uint32_t pack_bf16x2(float lo, float hi) {
    uint32_t d;
    asm("cvt.rn.bf16x2.f32 %0, %1, %2;" : "=r"(d) : "f"(hi), "f"(lo));
    return d;
}

// ---------------- scratch (device globals) ----------------------------------
__device__ __align__(256) __nv_bfloat16 g_xs[2ull * SEQ * DM];    // 16 MB
__device__ __align__(256) __nv_bfloat16 g_wt[2ull * NCAT * DM];   // 50 MB
__device__ __align__(256) __nv_bfloat16 g_ot[2ull * DM * DM];     // 16 MB
__device__ __align__(256) __nv_bfloat16 g_ys[2ull * SEQ * DM];    // 16 MB
__device__ __align__(256) __nv_bfloat16 g_qs2[2ull * NH * SEQ * DQK];  // 16 MB
__device__ __align__(256) __nv_bfloat16 g_ks2[2ull * NH * SEQ * DQK];  // 16 MB
__device__ __align__(256) __nv_bfloat16 g_vs2[2ull * NH * SEQ * DV];   // 16 MB
__device__ __align__(256) float g_pqkv[(size_t)SEQ * NCAT];       // 50 MB
__device__ float g_sin[SEQ * 64];
__device__ float g_cos[SEQ * 64];

// ---------------- bf16x2 split ----------------------------------------------
__device__ __forceinline__ void split2(float x, __nv_bfloat16& b0, __nv_bfloat16& b1) {
    b0 = __float2bfloat16(x);
    float r = x - __bfloat162float(b0);
    b1 = __float2bfloat16(r);
}

// ---------------- RoPE sin/cos table ----------------------------------------
__global__ void rope_table_kernel(const float* __restrict__ theta_p) {
    int idx = blockIdx.x * blockDim.x + threadIdx.x;
    if (idx >= SEQ * 64) return;
    int j = idx & 63;
    int s = idx >> 6;
    float theta = *theta_p;
    float rate = theta * (-(float)j / 64.0f);
    float rot  = (float)s * rate;
    double rd = (double)rot;
    g_sin[idx] = (float)sin(rd);
    g_cos[idx] = (float)cos(rd);
}

// ---------------- split kernels ---------------------------------------------
__global__ void split_x_kernel(const float* __restrict__ x) {
    int i = blockIdx.x * blockDim.x + threadIdx.x;
    const size_t N = (size_t)SEQ * DM;
    __nv_bfloat16 b0, b1;
    split2(x[i], b0, b1);
    g_xs[i] = b0; g_xs[N + i] = b1;
}

// ---------------- weight transpose + split ----------------------------------
__global__ void trans_w_kernel(const float* __restrict__ q,
                               const float* __restrict__ k,
                               const float* __restrict__ v) {
    __shared__ float t[32][33];
    int bz = blockIdx.z;
    int which = bz >> 4, h = bz & 15;
    const float* W = (which == 0 ? q : which == 1 ? k : v) + (size_t)h * DM * DQK;
    int kk0 = blockIdx.x * 32, e0 = blockIdx.y * 32;
    int tx = threadIdx.x, ty = threadIdx.y;
    const size_t WS = (size_t)NCAT * DM;
#pragma unroll
    for (int r = 0; r < 4; r++)
        t[ty + 8 * r][tx] = W[(size_t)(kk0 + ty + 8 * r) * DQK + e0 + tx];
    __syncthreads();
    size_t nbase = (size_t)which * 2048 + h * 128 + e0;
#pragma unroll
    for (int r = 0; r < 4; r++) {
        float xv = t[tx][ty + 8 * r];
        __nv_bfloat16 b0, b1;
        split2(xv, b0, b1);
        size_t o = (nbase + ty + 8 * r) * DM + kk0 + tx;
        g_wt[o] = b0; g_wt[WS + o] = b1;
    }
}
__global__ void trans_o_kernel(const float* __restrict__ o) {
    __shared__ float t[32][33];
    int h = blockIdx.z;
    const float* O = o + (size_t)h * DV * DM;
    int dm0 = blockIdx.x * 32, v0 = blockIdx.y * 32;
    int tx = threadIdx.x, ty = threadIdx.y;
    const size_t OS = (size_t)DM * DM;
#pragma unroll
    for (int r = 0; r < 4; r++)
        t[ty + 8 * r][tx] = O[(size_t)(v0 + ty + 8 * r) * DM + dm0 + tx];
    __syncthreads();
#pragma unroll
    for (int r = 0; r < 4; r++) {
        float xv = t[tx][ty + 8 * r];
        __nv_bfloat16 b0, b1;
        split2(xv, b0, b1);
        size_t oo = (size_t)(dm0 + ty + 8 * r) * DM + h * 128 + v0 + tx;
        g_ot[oo] = b0; g_ot[OS + oo] = b1;
    }
}

// ---------------- bf16x2 mma.sync GEMM ---------------------------------------
#define GSM_BYTES (2 * 98304)

__global__ void __launch_bounds__(256, 1) gemm2_kernel(float* Cout, int mode) {
    extern __shared__ char gsm[];
    const __nv_bfloat16 *A3, *B3;
    size_t As, Bs;
    float* C; int ldc; float alpha;
    if (mode == 0) {
        A3 = g_xs; As = (size_t)SEQ * DM;
        B3 = g_wt; Bs = (size_t)NCAT * DM;
        C = g_pqkv; ldc = NCAT; alpha = 1.0f;
    } else {
        A3 = g_ys; As = (size_t)SEQ * DM;
        B3 = g_ot; Bs = (size_t)DM * DM;
        C = Cout; ldc = DM; alpha = 1.0f / 2048.0f;
    }

    uint32_t sb = smem_u32(gsm);
    int tid = threadIdx.x;
    int lane = tid & 31, wid = tid >> 5;
    int wm = wid >> 1, wn = wid & 1;
    int m0 = blockIdx.x * 256, n0 = blockIdx.y * 128;

    float acc[4][8][4];
#pragma unroll
    for (int i = 0; i < 4; i++)
#pragma unroll
        for (int j = 0; j < 8; j++)
#pragma unroll
            for (int r = 0; r < 4; r++) acc[i][j][r] = 0.0f;

    auto load_stage = [&](int s, int kc) {
        int k0 = kc * 64;
#pragma unroll
        for (int p = 0; p < 2; p++) {
            const __nv_bfloat16* gp = A3 + p * As + (size_t)m0 * DM + k0;
            uint32_t base = sb + s * 98304 + p * 32768;
#pragma unroll
            for (int i = 0; i < 8; i++) {
                int idx = i * 256 + tid;
                int row = idx >> 3, c = idx & 7;
                uint32_t dst = base + row * 128 + ((c ^ (row & 7)) << 4);
                CP_ASYNC16(dst, gp + (size_t)row * DM + c * 8);
            }
        }
#pragma unroll
        for (int p = 0; p < 2; p++) {
            const __nv_bfloat16* gp = B3 + p * Bs + (size_t)n0 * DM + k0;
            uint32_t base = sb + s * 98304 + 65536 + p * 16384;
#pragma unroll
            for (int i = 0; i < 4; i++) {
                int idx = i * 256 + tid;
                int row = idx >> 3, c = idx & 7;
                uint32_t dst = base + row * 128 + ((c ^ (row & 7)) << 4);
                CP_ASYNC16(dst, gp + (size_t)row * DM + c * 8);
            }
        }
    };

    load_stage(0, 0); CP_COMMIT();

    for (int kc = 0; kc < 32; kc++) {
        int s = kc & 1;
        if (kc + 1 < 32) { load_stage(s ^ 1, kc + 1); CP_COMMIT(); CP_WAIT(1); }
        else            { CP_WAIT(0); }
        __syncthreads();

        uint32_t stage = sb + s * 98304;
#pragma unroll
        for (int ks = 0; ks < 4; ks++) {
            uint32_t a[2][4][4];
#pragma unroll
            for (int p = 0; p < 2; p++)
#pragma unroll
                for (int mf = 0; mf < 4; mf++) {
                    int row = wm * 64 + mf * 16 + (lane & 15);
                    int c = ks * 2 + ((lane >> 4) & 1);
                    uint32_t addr = stage + p * 32768 + row * 128 +
                                    ((c ^ (row & 7)) << 4);
                    ldsm4(a[p][mf], addr);
                }
            uint32_t b[2][4][4];
#pragma unroll
            for (int p = 0; p < 2; p++)
#pragma unroll
                for (int nf2 = 0; nf2 < 4; nf2++) {
                    int row = wn * 64 + nf2 * 16 + (lane & 7) + ((lane >> 4) & 1) * 8;
                    int c = ks * 2 + ((lane >> 3) & 1);
                    uint32_t addr = stage + 65536 + p * 16384 + row * 128 +
                                    ((c ^ (row & 7)) << 4);
                    ldsm4(b[p][nf2], addr);
                }
#pragma unroll
            for (int mf = 0; mf < 4; mf++)
#pragma unroll
                for (int nf2 = 0; nf2 < 4; nf2++) {
                    mma_bf16(acc[mf][2 * nf2 + 0], a[0][mf], b[0][nf2][0], b[0][nf2][1]);
                    mma_bf16(acc[mf][2 * nf2 + 1], a[0][mf], b[0][nf2][2], b[0][nf2][3]);
                    mma_bf16(acc[mf][2 * nf2 + 0], a[0][mf], b[1][nf2][0], b[1][nf2][1]);
                    mma_bf16(acc[mf][2 * nf2 + 1], a[0][mf], b[1][nf2][2], b[1][nf2][3]);
                    mma_bf16(acc[mf][2 * nf2 + 0], a[1][mf], b[0][nf2][0], b[0][nf2][1]);
                    mma_bf16(acc[mf][2 * nf2 + 1], a[1][mf], b[0][nf2][2], b[0][nf2][3]);
                }
        }
        __syncthreads();
    }

#pragma unroll
    for (int mf = 0; mf < 4; mf++) {
        int r0 = m0 + wm * 64 + mf * 16 + (lane >> 2);
#pragma unroll
        for (int nf = 0; nf < 8; nf++) {
            int cb = n0 + wn * 64 + nf * 8 + (lane & 3) * 2;
            float2 v01 = make_float2(acc[mf][nf][0] * alpha, acc[mf][nf][1] * alpha);
            float2 v23 = make_float2(acc[mf][nf][2] * alpha, acc[mf][nf][3] * alpha);
            *(float2*)&C[(size_t)r0 * ldc + cb] = v01;
            *(float2*)&C[(size_t)(r0 + 8) * ldc + cb] = v23;
        }
    }
}

// ---------------- prep: RoPE + bf16x2 split of q,k,v -------------------------
__global__ void prep_attn_kernel() {
    int g = blockIdx.x * blockDim.x + threadIdx.x;   // 3*16*2048*64 threads
    int j = g & 63;
    int s = (g >> 6) & (SEQ - 1);
    int h = (g >> 17) & (NH - 1);
    int t = g >> 21;                                  // 0=q, 1=k, 2=v
    const float* row = g_pqkv + (size_t)s * NCAT + t * 2048 + h * 128;
    size_t obase = ((size_t)h * SEQ + s) * 128;
    const size_t HSD = (size_t)NH * SEQ * 128;
    __nv_bfloat16 b0, b1;
    if (t < 2) {
        float x1 = row[j], x2 = row[j + 64];
        float sn = g_sin[s * 64 + j], cs = g_cos[s * 64 + j];
        const float dq4 = 3.3635856610148585f;  // 128^0.25
        float r1 = (cs * x1 - sn * x2) / dq4;
        float r2 = (sn * x1 + cs * x2) / dq4;
        __nv_bfloat16* dst = (t == 0 ? g_qs2 : g_ks2);
        split2(r1, b0, b1); dst[obase + j] = b0; dst[HSD + obase + j] = b1;
        split2(r2, b0, b1); dst[obase + j + 64] = b0; dst[HSD + obase + j + 64] = b1;
    } else {
        float v1 = row[j], v2 = row[j + 64];
        split2(v1, b0, b1); g_vs2[obase + j] = b0; g_vs2[HSD + obase + j] = b1;
        split2(v2, b0, b1); g_vs2[obase + j + 64] = b0; g_vs2[HSD + obase + j + 64] = b1;
    }
}

// ---------------- flash attention (bf16x2 mma.sync) --------------------------
// CTA: 8 warps, q-tile 128 (16 q-rows per warp), k-tiles of 64, double-buffered.
// smem: Q 2 planes 64KB resident; 2 stages x (K 2pl 32KB + V 2pl 32KB) = 128KB.
#define ATTN_SMEM 196608

__global__ void __launch_bounds__(256, 1) attn_kernel() {
    extern __shared__ char asmem[];
    uint32_t sb = smem_u32(asmem);
    int tid = threadIdx.x, lane = tid & 31, wq = tid >> 5;
    int h = blockIdx.x;
    int qt = 15 - (int)blockIdx.y;    // LPT: heavy q-tiles first
    int q0 = qt * 128;
    const size_t HSD = (size_t)NH * SEQ * 128;

    const __nv_bfloat16* Qg = g_qs2 + ((size_t)h * SEQ + q0) * 128;
    const __nv_bfloat16* Kg = g_ks2 + (size_t)h * SEQ * 128;
    const __nv_bfloat16* Vg = g_vs2 + (size_t)h * SEQ * 128;

    const uint32_t Qb = sb;                          // [p][128 rows][256B]
    const uint32_t St0 = sb + 65536, St1 = sb + 131072;

    // swizzled address of 16B chunk (row, c) ; 16 chunks per 256B row
#define SWZ(base, row, c) ((base) + (row) * 256 + ((((c) ^ (((row) & 7) << 1)) & 15) << 4))

    // load Q (both planes): 4096 chunks
#pragma unroll
    for (int i = 0; i < 16; i++) {
        int idx = i * 256 + tid;
        int p = idx >> 11, rem = idx & 2047, row = rem >> 4, c = rem & 15;
        CP_ASYNC16(SWZ(Qb + p * 32768, row, c),
                   (const char*)(Qg + p * HSD) + row * 256 + c * 16);
    }
    int nkt = 2 * qt + 2;

    auto loadKV = [&](uint32_t stage, int kt) {
        int kb = kt * 64;
#pragma unroll
        for (int i = 0; i < 16; i++) {
            int idx = i * 256 + tid;
            int tile = idx >> 11;                     // 0:K 1:V
            int p = (idx >> 10) & 1, row = (idx >> 4) & 63, c = idx & 15;
            const __nv_bfloat16* src =
                (tile ? Vg : Kg) + p * HSD + (size_t)(kb + row) * 128;
            CP_ASYNC16(SWZ(stage + tile * 32768 + p * 16384, row, c),
                       (const char*)src + c * 16);
        }
    };
    loadKV(St0, 0); CP_COMMIT();
    loadKV(St1, 1); CP_COMMIT();

    float y[16][4];
#pragma unroll
    for (int i = 0; i < 16; i++)
#pragma unroll
        for (int r = 0; r < 4; r++) y[i][r] = 0.0f;
    float mr0 = -INFINITY, mr1 = -INFINITY, l0 = 0.0f, l1 = 0.0f;
    int qrow0 = q0 + wq * 16 + (lane >> 2);  // second row: +8

    for (int kt = 0; kt < nkt; kt++) {
        CP_WAIT(1);
        __syncthreads();
        uint32_t S = (kt & 1) ? St1 : St0;
        int kbase = kt * 64;

        // ---- S = Q K^T (bf16x2, 3 products) ----
        float sacc[8][4];
#pragma unroll
        for (int i = 0; i < 8; i++)
#pragma unroll
            for (int r = 0; r < 4; r++) sacc[i][r] = 0.0f;

#pragma unroll
        for (int kf = 0; kf < 8; kf++) {
            uint32_t aq0[4], aq1[4];
            {
                int row = wq * 16 + (lane & 15);
                int c = kf * 2 + (lane >> 4);
                ldsm4(aq0, SWZ(Qb, row, c));
                ldsm4(aq1, SWZ(Qb + 32768, row, c));
            }
#pragma unroll
            for (int ng = 0; ng < 4; ng++) {
                uint32_t kb0[4], kb1[4];
                int row = ng * 16 + (lane & 7) + ((lane >> 4) & 1) * 8;
                int c = kf * 2 + ((lane >> 3) & 1);
                ldsm4(kb0, SWZ(S, row, c));
                ldsm4(kb1, SWZ(S + 16384, row, c));
                mma_bf16(sacc[2 * ng + 0], aq0, kb0[0], kb0[1]);
                mma_bf16(sacc[2 * ng + 1], aq0, kb0[2], kb0[3]);
                mma_bf16(sacc[2 * ng + 0], aq0, kb1[0], kb1[1]);
                mma_bf16(sacc[2 * ng + 1], aq0, kb1[2], kb1[3]);
                mma_bf16(sacc[2 * ng + 0], aq1, kb0[0], kb0[1]);
                mma_bf16(sacc[2 * ng + 1], aq1, kb0[2], kb0[3]);
            }
        }

        // ---- mask (diagonal tiles only) ----
        if (kbase + 64 > q0 + wq * 16) {
#pragma unroll
            for (int nf = 0; nf < 8; nf++) {
                int col = kbase + nf * 8 + (lane & 3) * 2;
                if (col > qrow0)         sacc[nf][0] -= 1.0e9f;
                if (col + 1 > qrow0)     sacc[nf][1] -= 1.0e9f;
                if (col > qrow0 + 8)     sacc[nf][2] -= 1.0e9f;
                if (col + 1 > qrow0 + 8) sacc[nf][3] -= 1.0e9f;
            }
        }

        // ---- online softmax ----
        float mx0 = -INFINITY, mx1 = -INFINITY;
#pragma unroll
        for (int nf = 0; nf < 8; nf++) {
            mx0 = fmaxf(mx0, fmaxf(sacc[nf][0], sacc[nf][1]));
            mx1 = fmaxf(mx1, fmaxf(sacc[nf][2], sacc[nf][3]));
        }
        mx0 = fmaxf(mx0, __shfl_xor_sync(0xffffffffu, mx0, 1));
        mx0 = fmaxf(mx0, __shfl_xor_sync(0xffffffffu, mx0, 2));
        mx1 = fmaxf(mx1, __shfl_xor_sync(0xffffffffu, mx1, 1));
        mx1 = fmaxf(mx1, __shfl_xor_sync(0xffffffffu, mx1, 2));
        float mn0 = fmaxf(mr0, mx0), mn1 = fmaxf(mr1, mx1);
        float c0 = __expf(mr0 - mn0), c1 = __expf(mr1 - mn1);
        float ls0 = 0.0f, ls1 = 0.0f;
#pragma unroll
        for (int nf = 0; nf < 8; nf++) {
            sacc[nf][0] = __expf(sacc[nf][0] - mn0);
            sacc[nf][1] = __expf(sacc[nf][1] - mn0);
            sacc[nf][2] = __expf(sacc[nf][2] - mn1);
            sacc[nf][3] = __expf(sacc[nf][3] - mn1);
            ls0 += sacc[nf][0] + sacc[nf][1];
            ls1 += sacc[nf][2] + sacc[nf][3];
        }
        ls0 += __shfl_xor_sync(0xffffffffu, ls0, 1);
        ls0 += __shfl_xor_sync(0xffffffffu, ls0, 2);
        ls1 += __shfl_xor_sync(0xffffffffu, ls1, 1);
        ls1 += __shfl_xor_sync(0xffffffffu, ls1, 2);
        l0 = l0 * c0 + ls0; l1 = l1 * c1 + ls1;
        mr0 = mn0; mr1 = mn1;
#pragma unroll
        for (int i = 0; i < 16; i++) {
            y[i][0] *= c0; y[i][1] *= c0; y[i][2] *= c1; y[i][3] *= c1;
        }

        // ---- Y += P V (bf16x2, 3 products) ----
#pragma unroll
        for (int kf2 = 0; kf2 < 4; kf2++) {
            uint32_t p0[4], p1[4];
#pragma unroll
            for (int half = 0; half < 2; half++) {
                float f0 = sacc[2 * kf2 + half][0], f1 = sacc[2 * kf2 + half][1];
                float f2 = sacc[2 * kf2 + half][2], f3 = sacc[2 * kf2 + half][3];
                float g0 = f0 - __bfloat162float(__float2bfloat16(f0));
                float g1 = f1 - __bfloat162float(__float2bfloat16(f1));
                float g2 = f2 - __bfloat162float(__float2bfloat16(f2));
                float g3 = f3 - __bfloat162float(__float2bfloat16(f3));
                p0[2 * half + 0] = pack_bf16x2(f0, f1);
                p0[2 * half + 1] = pack_bf16x2(f2, f3);
                p1[2 * half + 0] = pack_bf16x2(g0, g1);
                p1[2 * half + 1] = pack_bf16x2(g2, g3);
            }
            // reorder: A regs = {a0(r,k0-7), a1(r+8,k0-7), a2(r,k8-15), a3(r+8,k8-15)}
            uint32_t a0[4] = {p0[0], p0[1], p0[2], p0[3]};
            uint32_t a1[4] = {p1[0], p1[1], p1[2], p1[3]};
#pragma unroll
            for (int ng = 0; ng < 8; ng++) {
                uint32_t vb0[4], vb1[4];
                int row = kf2 * 16 + (lane & 15);
                int c = ng * 2 + (lane >> 4);
                ldsm4t(vb0, SWZ(S + 32768, row, c));
                ldsm4t(vb1, SWZ(S + 49152, row, c));
                mma_bf16(y[2 * ng + 0], a0, vb0[0], vb0[1]);
                mma_bf16(y[2 * ng + 1], a0, vb0[2], vb0[3]);
                mma_bf16(y[2 * ng + 0], a0, vb1[0], vb1[1]);
                mma_bf16(y[2 * ng + 1], a0, vb1[2], vb1[3]);
                mma_bf16(y[2 * ng + 0], a1, vb0[0], vb0[1]);
                mma_bf16(y[2 * ng + 1], a1, vb0[2], vb0[3]);
            }
        }

        __syncthreads();
        if (kt + 2 < nkt) loadKV((kt & 1) ? St1 : St0, kt + 2);
        CP_COMMIT();
    }

    // ---- epilogue: normalize + bf16x2 split, write g_ys planes ----
    float inv0 = 1.0f / l0, inv1 = 1.0f / l1;
    int s0 = q0 + wq * 16 + (lane >> 2);
    const size_t N = (size_t)SEQ * DM;
#pragma unroll
    for (int nf = 0; nf < 16; nf++) {
        int col = h * 128 + nf * 8 + (lane & 3) * 2;
        {
            float f0 = y[nf][0] * inv0, f1 = y[nf][1] * inv0;
            __nv_bfloat16 a0 = __float2bfloat16(f0), a1 = __float2bfloat16(f1);
            __nv_bfloat162 hi; hi.x = a0; hi.y = a1;
            __nv_bfloat162 lo;
            lo.x = __float2bfloat16(f0 - __bfloat162float(a0));
            lo.y = __float2bfloat16(f1 - __bfloat162float(a1));
            *(__nv_bfloat162*)&g_ys[(size_t)s0 * DM + col] = hi;
            *(__nv_bfloat162*)&g_ys[N + (size_t)s0 * DM + col] = lo;
        }
        {
            float f0 = y[nf][2] * inv1, f1 = y[nf][3] * inv1;
            __nv_bfloat16 a0 = __float2bfloat16(f0), a1 = __float2bfloat16(f1);
            __nv_bfloat162 hi; hi.x = a0; hi.y = a1;
            __nv_bfloat162 lo;
            lo.x = __float2bfloat16(f0 - __bfloat162float(a0));
            lo.y = __float2bfloat16(f1 - __bfloat162float(a1));
            *(__nv_bfloat162*)&g_ys[(size_t)(s0 + 8) * DM + col] = hi;
            *(__nv_bfloat162*)&g_ys[N + (size_t)(s0 + 8) * DM + col] = lo;
        }
    }
#undef SWZ
}

// ---------------- launch ----------------------------------------------------
extern "C" void kernel_launch(void* const* d_in, const int* in_sizes, int n_in,
                              void* d_out, int out_size) {
    const float* x     = (const float*)d_in[0];
    const float* q     = (const float*)d_in[1];
    const float* k     = (const float*)d_in[2];
    const float* v     = (const float*)d_in[3];
    const float* o     = (const float*)d_in[4];
    const float* theta = (const float*)d_in[5];
    float* z = (float*)d_out;

    cudaFuncSetAttribute(attn_kernel,
                         cudaFuncAttributeMaxDynamicSharedMemorySize, ATTN_SMEM);
    cudaFuncSetAttribute(gemm2_kernel,
                         cudaFuncAttributeMaxDynamicSharedMemorySize, GSM_BYTES);

    rope_table_kernel<<<(SEQ * 64 + 255) / 256, 256>>>(theta);
    split_x_kernel<<<(SEQ * DM) / 256, 256>>>(x);
    trans_w_kernel<<<dim3(64, 4, 48), dim3(32, 8)>>>(q, k, v);
    trans_o_kernel<<<dim3(64, 4, 16), dim3(32, 8)>>>(o);
    gemm2_kernel<<<dim3(8, 48), 256, GSM_BYTES>>>(nullptr, 0);
    prep_attn_kernel<<<(3 * NH * SEQ * 64) / 256, 256>>>();
    attn_kernel<<<dim3(NH, 16), 256, ATTN_SMEM>>>();
    gemm2_kernel<<<dim3(8, 16), 256, GSM_BYTES>>>(z, 1);
}